// round 1
// baseline (speedup 1.0000x reference)
#include <cuda_runtime.h>
#include <math.h>

#define Bb   8
#define Ss   2048
#define Dd   256
#define Hh   8
#define DKk  32
#define DFFf 1024
#define Ll   5
#define Mm   (Bb*Ss)   // 16384 rows

// ---------------- scratch (device globals; no allocation allowed) ----------
__device__ float g_X [(size_t)Mm*Dd];
__device__ float g_Qb[(size_t)Mm*Dd];
__device__ float g_Kb[(size_t)Mm*Dd];
__device__ float g_Vb[(size_t)Mm*Dd];
__device__ float g_Cb[(size_t)Mm*Dd];
__device__ float g_Tb[(size_t)Mm*Dd];
__device__ float g_Hf[(size_t)Mm*DFFf];

// ---------------- GEMM: C[M,N] = A[M,K] @ W[K,N] + bias, optional GELU -----
__global__ __launch_bounds__(256) void gemm_bias_act(
    const float* __restrict__ A, const float* __restrict__ W,
    const float* __restrict__ bias, float* __restrict__ C,
    int M, int N, int K, int act)
{
    __shared__ float As[16][68];   // padded to kill store conflicts
    __shared__ float Bs[16][64];

    const int tid  = threadIdx.x;
    const int brow = blockIdx.y * 64;
    const int bcol = blockIdx.x * 64;

    const int a_r = tid >> 2,  a_c = (tid & 3)  << 2;  // A tile: 64x16 via float4
    const int b_r = tid >> 4,  b_c = (tid & 15) << 2;  // B tile: 16x64 via float4
    const int tr  = (tid >> 4) << 2;                   // 4x4 register tile
    const int tc  = (tid & 15) << 2;

    float acc[4][4] = {};

    const float* Ap = A + (size_t)(brow + a_r) * K + a_c;
    const float* Wp = W + (size_t)b_r * N + bcol + b_c;

    for (int k0 = 0; k0 < K; k0 += 16) {
        float4 av = *(const float4*)(Ap + k0);
        As[a_c+0][a_r] = av.x; As[a_c+1][a_r] = av.y;
        As[a_c+2][a_r] = av.z; As[a_c+3][a_r] = av.w;
        *(float4*)&Bs[b_r][b_c] = *(const float4*)(Wp + (size_t)k0 * N);
        __syncthreads();
#pragma unroll
        for (int k = 0; k < 16; k++) {
            float4 a  = *(const float4*)&As[k][tr];
            float4 bv = *(const float4*)&Bs[k][tc];
            float ar[4] = {a.x, a.y, a.z, a.w};
            float br[4] = {bv.x, bv.y, bv.z, bv.w};
#pragma unroll
            for (int i = 0; i < 4; i++)
#pragma unroll
                for (int j = 0; j < 4; j++)
                    acc[i][j] = fmaf(ar[i], br[j], acc[i][j]);
        }
        __syncthreads();
    }

    float4 bb = *(const float4*)&bias[bcol + tc];
    float bv4[4] = {bb.x, bb.y, bb.z, bb.w};
#pragma unroll
    for (int i = 0; i < 4; i++) {
        const int row = brow + tr + i;
        float4 o;
        float v[4];
#pragma unroll
        for (int j = 0; j < 4; j++) {
            float x = acc[i][j] + bv4[j];
            if (act == 1) x = 0.5f * x * (1.0f + erff(x * 0.70710678118654752f));
            v[j] = x;
        }
        o.x = v[0]; o.y = v[1]; o.z = v[2]; o.w = v[3];
        *(float4*)&C[(size_t)row * N + bcol + tc] = o;
    }
}

// ---------------- Flash attention with additive bias -----------------------
// grid: (S/64, H, B), block: 128 threads. Thread pair (2q,2q+1) owns query q;
// each handles 16 of the 32 dk output components and 32 of the 64 tile keys.
__global__ __launch_bounds__(128) void attn_kernel(
    const float* __restrict__ Q, const float* __restrict__ K,
    const float* __restrict__ V, const float* __restrict__ sph,
    float* __restrict__ O)
{
    __shared__ float Ks[64][36];
    __shared__ float Vs[64][36];
    __shared__ float Ps[64][65];   // bias tile, then prob tile

    const int qb  = blockIdx.x, h = blockIdx.y, b = blockIdx.z;
    const int tid = threadIdx.x;
    const int q    = tid >> 1;
    const int half = tid & 1;
    const int q0   = qb * 64;

    const float* qp = Q + (size_t)((b*Ss + q0 + q)*Dd + h*DKk);
    float qreg[32];
#pragma unroll
    for (int d = 0; d < 32; d++) qreg[d] = qp[d] * 0.17677669529663687f; // 1/sqrt(32)

    float o[16];
#pragma unroll
    for (int i = 0; i < 16; i++) o[i] = 0.f;
    float m = -INFINITY, l = 0.f;

    const float* sphb = sph + (size_t)b*Ss*Ss + (size_t)q0*Ss;

    for (int kb = 0; kb < Ss/64; kb++) {
        const int k0 = kb * 64;
        // cooperative coalesced loads
        for (int i = tid; i < 64*32; i += 128) {
            int r = i >> 5, c = i & 31;
            int gi = (b*Ss + k0 + r)*Dd + h*DKk + c;
            Ks[r][c] = K[gi];
            Vs[r][c] = V[gi];
        }
        for (int i = tid; i < 64*64; i += 128) {
            int r = i >> 6, c = i & 63;
            Ps[r][c] = sphb[(size_t)r*Ss + k0 + c];
        }
        __syncthreads();

        float sc[32];
#pragma unroll
        for (int kk = 0; kk < 32; kk++) {
            const int k = half*32 + kk;
            float s = Ps[q][k];
#pragma unroll
            for (int d = 0; d < 32; d++) s = fmaf(qreg[d], Ks[k][d], s);
            sc[kk] = s;
        }

        float lm = sc[0];
#pragma unroll
        for (int kk = 1; kk < 32; kk++) lm = fmaxf(lm, sc[kk]);
        lm = fmaxf(lm, __shfl_xor_sync(0xffffffffu, lm, 1));
        const float mnew  = fmaxf(m, lm);
        const float alpha = __expf(m - mnew);

        float psum = 0.f;
#pragma unroll
        for (int kk = 0; kk < 32; kk++) {
            float p = __expf(sc[kk] - mnew);
            Ps[q][half*32 + kk] = p;
            psum += p;
        }
        psum += __shfl_xor_sync(0xffffffffu, psum, 1);
        l = l * alpha + psum;
        m = mnew;
#pragma unroll
        for (int i = 0; i < 16; i++) o[i] *= alpha;

        __syncwarp();   // partner-thread Ps writes (same warp) visible

#pragma unroll 4
        for (int k = 0; k < 64; k++) {
            const float p = Ps[q][k];
            const float4* vp = (const float4*)&Vs[k][half*16];
#pragma unroll
            for (int jj = 0; jj < 4; jj++) {
                float4 vv = vp[jj];
                o[jj*4+0] = fmaf(p, vv.x, o[jj*4+0]);
                o[jj*4+1] = fmaf(p, vv.y, o[jj*4+1]);
                o[jj*4+2] = fmaf(p, vv.z, o[jj*4+2]);
                o[jj*4+3] = fmaf(p, vv.w, o[jj*4+3]);
            }
        }
        __syncthreads();
    }

    const float inv = 1.f / l;
    float* op = O + (size_t)((b*Ss + q0 + q)*Dd + h*DKk + half*16);
#pragma unroll
    for (int i = 0; i < 16; i++) op[i] = o[i] * inv;
}

// ---------------- fused residual + LayerNorm -------------------------------
__global__ __launch_bounds__(256) void add_ln(
    const float* __restrict__ x, const float* __restrict__ s,
    const float* __restrict__ g, const float* __restrict__ bb,
    float* __restrict__ out)
{
    const int row = blockIdx.x;
    const int t   = threadIdx.x;
    const size_t idx = (size_t)row * Dd + t;
    const float v = x[idx] + s[idx];

    float sum = v, sq = v * v;
#pragma unroll
    for (int o = 16; o; o >>= 1) {
        sum += __shfl_xor_sync(0xffffffffu, sum, o);
        sq  += __shfl_xor_sync(0xffffffffu, sq,  o);
    }
    __shared__ float ssum[8], ssq[8];
    const int w = t >> 5, lane = t & 31;
    if (lane == 0) { ssum[w] = sum; ssq[w] = sq; }
    __syncthreads();
    if (w == 0) {
        float a = (lane < 8) ? ssum[lane] : 0.f;
        float c = (lane < 8) ? ssq[lane]  : 0.f;
#pragma unroll
        for (int o = 4; o; o >>= 1) {
            a += __shfl_xor_sync(0xffffffffu, a, o);
            c += __shfl_xor_sync(0xffffffffu, c, o);
        }
        if (lane == 0) { ssum[0] = a; ssq[0] = c; }
    }
    __syncthreads();
    const float mu  = ssum[0] * (1.f / Dd);
    const float var = ssq[0]  * (1.f / Dd) - mu * mu;
    out[idx] = (v - mu) * rsqrtf(var + 1e-5f) * g[t] + bb[t];
}

// ---------------- driver ----------------------------------------------------
extern "C" void kernel_launch(void* const* d_in, const int* in_sizes, int n_in,
                              void* d_out, int out_size)
{
    const float* src = (const float*)d_in[0];
    const float* sph = (const float*)d_in[1];
    const float* Wq  = (const float*)d_in[2];
    const float* bq  = (const float*)d_in[3];
    const float* Wk  = (const float*)d_in[4];
    const float* bk  = (const float*)d_in[5];
    const float* Wv  = (const float*)d_in[6];
    const float* bv  = (const float*)d_in[7];
    const float* Wo  = (const float*)d_in[8];
    const float* bo  = (const float*)d_in[9];
    const float* W1  = (const float*)d_in[10];
    const float* b1  = (const float*)d_in[11];
    const float* W2  = (const float*)d_in[12];
    const float* b2  = (const float*)d_in[13];
    const float* g1  = (const float*)d_in[14];
    const float* be1 = (const float*)d_in[15];
    const float* g2  = (const float*)d_in[16];
    const float* be2 = (const float*)d_in[17];
    float* out = (float*)d_out;

    float *X, *Qb, *Kb, *Vb, *Cb, *Tb, *Hb;
    cudaGetSymbolAddress((void**)&X,  g_X);
    cudaGetSymbolAddress((void**)&Qb, g_Qb);
    cudaGetSymbolAddress((void**)&Kb, g_Kb);
    cudaGetSymbolAddress((void**)&Vb, g_Vb);
    cudaGetSymbolAddress((void**)&Cb, g_Cb);
    cudaGetSymbolAddress((void**)&Tb, g_Tb);
    cudaGetSymbolAddress((void**)&Hb, g_Hf);

    cudaMemcpyAsync(X, src, sizeof(float) * (size_t)Mm * Dd,
                    cudaMemcpyDeviceToDevice);

    const dim3 gD (Dd/64,   Mm/64);   // 4 x 256 blocks
    const dim3 gF1(DFFf/64, Mm/64);   // 16 x 256 blocks
    const dim3 gAt(Ss/64, Hh, Bb);    // 32 x 8 x 8

    for (int i = 0; i < Ll; i++) {
        const float* wq = Wq + (size_t)i*Dd*Dd;
        const float* wk = Wk + (size_t)i*Dd*Dd;
        const float* wv = Wv + (size_t)i*Dd*Dd;
        const float* wo = Wo + (size_t)i*Dd*Dd;
        const float* w1 = W1 + (size_t)i*Dd*DFFf;
        const float* w2 = W2 + (size_t)i*DFFf*Dd;

        gemm_bias_act<<<gD, 256>>>(X,  wq, bq + i*Dd, Qb, Mm, Dd, Dd, 0);
        gemm_bias_act<<<gD, 256>>>(X,  wk, bk + i*Dd, Kb, Mm, Dd, Dd, 0);
        gemm_bias_act<<<gD, 256>>>(X,  wv, bv + i*Dd, Vb, Mm, Dd, Dd, 0);

        attn_kernel<<<gAt, 128>>>(Qb, Kb, Vb, sph, Cb);

        gemm_bias_act<<<gD, 256>>>(Cb, wo, bo + i*Dd, Tb, Mm, Dd, Dd, 0);
        add_ln<<<Mm, Dd>>>(X, Tb, g1 + i*Dd, be1 + i*Dd, X);

        gemm_bias_act<<<gF1, 256>>>(X,  w1, b1 + i*DFFf, Hb, Mm, DFFf, Dd, 1);
        gemm_bias_act<<<gD, 256>>>(Hb, w2, b2 + i*Dd,   Tb, Mm, Dd, DFFf, 0);
        add_ln<<<Mm, Dd>>>(X, Tb, g2 + i*Dd, be2 + i*Dd, (i == Ll-1) ? out : X);
    }
}

// round 4
// speedup vs baseline: 3.0907x; 3.0907x over previous
#include <cuda_runtime.h>
#include <math.h>
#include <stdint.h>

#define Bb   8
#define Ss   2048
#define Dd   256
#define Hh   8
#define DKk  32
#define DFFf 1024
#define Ll   5
#define Mm   (Bb*Ss)   // 16384 rows

// ---------------- scratch (device globals; no allocation allowed) ----------
__device__ float g_X [(size_t)Mm*Dd];
__device__ float g_Qb[(size_t)Mm*Dd];
__device__ float g_Kb[(size_t)Mm*Dd];
__device__ float g_Vb[(size_t)Mm*Dd];
__device__ float g_Cb[(size_t)Mm*Dd];
__device__ float g_Tb[(size_t)Mm*Dd];
__device__ float g_Hf[(size_t)Mm*DFFf];

// ======================= warp-MMA helpers (sm_80 baseline) ==================
__device__ __forceinline__ uint32_t cvta_s(const void* p) {
    return (uint32_t)__cvta_generic_to_shared(p);
}
__device__ __forceinline__ void ldsm4(uint32_t r[4], uint32_t a) {
    asm volatile("ldmatrix.sync.aligned.m8n8.x4.shared.b16 {%0,%1,%2,%3}, [%4];"
        : "=r"(r[0]), "=r"(r[1]), "=r"(r[2]), "=r"(r[3]) : "r"(a));
}
__device__ __forceinline__ void ldsm2(uint32_t r[2], uint32_t a) {
    asm volatile("ldmatrix.sync.aligned.m8n8.x2.shared.b16 {%0,%1}, [%2];"
        : "=r"(r[0]), "=r"(r[1]) : "r"(a));
}
__device__ __forceinline__ void ldsm2t(uint32_t r[2], uint32_t a) {
    asm volatile("ldmatrix.sync.aligned.m8n8.x2.trans.shared.b16 {%0,%1}, [%2];"
        : "=r"(r[0]), "=r"(r[1]) : "r"(a));
}
__device__ __forceinline__ void mma_bf(float c[4], const uint32_t a[4],
                                       const uint32_t b[2]) {
    asm volatile(
        "mma.sync.aligned.m16n8k16.row.col.f32.bf16.bf16.f32 "
        "{%0,%1,%2,%3},{%4,%5,%6,%7},{%8,%9},{%0,%1,%2,%3};"
        : "+f"(c[0]), "+f"(c[1]), "+f"(c[2]), "+f"(c[3])
        : "r"(a[0]), "r"(a[1]), "r"(a[2]), "r"(a[3]), "r"(b[0]), "r"(b[1]));
}
// pack two floats -> bf16x2 (x in low half = even column)
__device__ __forceinline__ uint32_t pack_bf(float x, float y) {
    uint32_t r;
    asm("cvt.rn.bf16x2.f32 %0, %1, %2;" : "=r"(r) : "f"(y), "f"(x));
    return r;
}
__device__ __forceinline__ void split_pair(float x, float y,
                                           uint32_t& hi, uint32_t& lo) {
    hi = pack_bf(x, y);
    float hx = __uint_as_float(hi << 16);
    float hy = __uint_as_float(hi & 0xFFFF0000u);
    lo = pack_bf(x - hx, y - hy);
}

// ============== bf16x3 tensor-core GEMM =====================================
// C[M,N] = A[M,K] @ W[K,N] + bias (+ exact GELU). Block tile 128x128, kt=32.
// 8 warps: wm = wid&3 (M), wn = wid>>2 (N). Warp tile 32x64.
#define APITCH 40    // uint16 pitch (pad 32 -> 40 : conflict-free ldmatrix)
#define BPITCH 136   // uint16 pitch for 128-wide B tile

__global__ __launch_bounds__(256) void gemm_mma(
    const float* __restrict__ A, const float* __restrict__ W,
    const float* __restrict__ bias, float* __restrict__ C,
    int N, int K, int act)
{
    __shared__ __align__(16) uint16_t Ahs[128*APITCH], Als[128*APITCH];
    __shared__ __align__(16) uint16_t Bhs[32*BPITCH],  Bls[32*BPITCH];

    const int tid  = threadIdx.x;
    const int lane = tid & 31, wid = tid >> 5;
    const int wm = wid & 3, wn = wid >> 2;
    const int m0 = blockIdx.y * 128, n0 = blockIdx.x * 128;

    const uint32_t aAh = cvta_s(Ahs), aAl = cvta_s(Als);
    const uint32_t aBh = cvta_s(Bhs), aBl = cvta_s(Bls);

    float acc[2][8][4];
#pragma unroll
    for (int i = 0; i < 2; i++)
#pragma unroll
        for (int j = 0; j < 8; j++)
#pragma unroll
            for (int u = 0; u < 4; u++) acc[i][j][u] = 0.f;

    for (int kt = 0; kt < K; kt += 32) {
        if (kt) __syncthreads();
        // ---- A tile 128x32 fp32 -> bf16 hi/lo ----
#pragma unroll
        for (int j = 0; j < 4; j++) {
            const int idx = tid + j * 256;          // 1024 float4
            const int r = idx >> 3, c4 = idx & 7;
            float4 v = *(const float4*)(A + (size_t)(m0 + r) * K + kt + c4 * 4);
            uint32_t h0, l0, h1, l1;
            split_pair(v.x, v.y, h0, l0);
            split_pair(v.z, v.w, h1, l1);
            const int off = r * APITCH + c4 * 4;    // uint16 units
            *(uint32_t*)&Ahs[off]     = h0;  *(uint32_t*)&Ahs[off + 2] = h1;
            *(uint32_t*)&Als[off]     = l0;  *(uint32_t*)&Als[off + 2] = l1;
        }
        // ---- B tile 32x128 ----
#pragma unroll
        for (int j = 0; j < 4; j++) {
            const int idx = tid + j * 256;
            const int r = idx >> 5, c4 = idx & 31;
            float4 v = *(const float4*)(W + (size_t)(kt + r) * N + n0 + c4 * 4);
            uint32_t h0, l0, h1, l1;
            split_pair(v.x, v.y, h0, l0);
            split_pair(v.z, v.w, h1, l1);
            const int off = r * BPITCH + c4 * 4;
            *(uint32_t*)&Bhs[off]     = h0;  *(uint32_t*)&Bhs[off + 2] = h1;
            *(uint32_t*)&Bls[off]     = l0;  *(uint32_t*)&Bls[off + 2] = l1;
        }
        __syncthreads();

#pragma unroll
        for (int kb = 0; kb < 2; kb++) {
            uint32_t ah[2][4], al[2][4];
#pragma unroll
            for (int i = 0; i < 2; i++) {
                const int row = wm * 32 + i * 16 + (lane & 15);
                const uint32_t byt =
                    (uint32_t)(row * APITCH + kb * 16 + ((lane >> 4) << 3)) * 2;
                ldsm4(ah[i], aAh + byt);
                ldsm4(al[i], aAl + byt);
            }
#pragma unroll
            for (int j = 0; j < 8; j++) {
                uint32_t bh[2], bl[2];
                const int krow = kb * 16 + (lane & 15);
                const uint32_t byt =
                    (uint32_t)(krow * BPITCH + wn * 64 + j * 8) * 2;
                ldsm2t(bh, aBh + byt);
                ldsm2t(bl, aBl + byt);
#pragma unroll
                for (int i = 0; i < 2; i++) {
                    mma_bf(acc[i][j], ah[i], bh);
                    mma_bf(acc[i][j], ah[i], bl);
                    mma_bf(acc[i][j], al[i], bh);
                }
            }
        }
    }

    // ---- epilogue: bias (+GELU), direct register -> gmem ----
    const int gid = lane >> 2, tig = lane & 3;
#pragma unroll
    for (int i = 0; i < 2; i++) {
        const int r0 = m0 + wm * 32 + i * 16 + gid;
#pragma unroll
        for (int j = 0; j < 8; j++) {
            const int col = n0 + wn * 64 + j * 8 + tig * 2;
            const float b0 = bias[col], b1 = bias[col + 1];
            float x0 = acc[i][j][0] + b0, x1 = acc[i][j][1] + b1;
            float x2 = acc[i][j][2] + b0, x3 = acc[i][j][3] + b1;
            if (act) {
                x0 = 0.5f * x0 * (1.f + erff(x0 * 0.70710678118654752f));
                x1 = 0.5f * x1 * (1.f + erff(x1 * 0.70710678118654752f));
                x2 = 0.5f * x2 * (1.f + erff(x2 * 0.70710678118654752f));
                x3 = 0.5f * x3 * (1.f + erff(x3 * 0.70710678118654752f));
            }
            *(float2*)(C + (size_t)r0 * N + col)       = make_float2(x0, x1);
            *(float2*)(C + (size_t)(r0 + 8) * N + col) = make_float2(x2, x3);
        }
    }
}

// ============== bf16x3 tensor-core flash attention ==========================
// grid (S/64, H, B), 128 threads (4 warps). Warp w owns q rows w*16..w*16+15.
#define KPITCH 40
#define SPITCH 68

__global__ __launch_bounds__(128) void attn_mma(
    const float* __restrict__ Q, const float* __restrict__ K,
    const float* __restrict__ V, const float* __restrict__ sph,
    float* __restrict__ O)
{
    __shared__ __align__(16) uint16_t Khs[64*KPITCH], Kls[64*KPITCH];
    __shared__ __align__(16) uint16_t Vhs[64*KPITCH], Vls[64*KPITCH];
    __shared__ __align__(16) float    Bs [64*SPITCH];

    const int tid  = threadIdx.x;
    const int lane = tid & 31, w = tid >> 5;
    const int gid = lane >> 2, tig = lane & 3;
    const int qb = blockIdx.x, h = blockIdx.y, b = blockIdx.z;
    const int q0 = qb * 64;

    const uint32_t aKh = cvta_s(Khs), aKl = cvta_s(Kls);
    const uint32_t aVh = cvta_s(Vhs), aVl = cvta_s(Vls);

    // ---- stage Q (scaled, split) into K buffers, grab fragments once ----
#pragma unroll
    for (int j = 0; j < 4; j++) {
        const int idx = tid + j * 128;               // 512 float4
        const int r = idx >> 3, c4 = idx & 7;
        float4 v = *(const float4*)(Q +
            (size_t)((b*Ss + q0 + r) * Dd + h * 32 + c4 * 4));
        const float sc = 0.17677669529663687f;       // 1/sqrt(32)
        v.x *= sc; v.y *= sc; v.z *= sc; v.w *= sc;
        uint32_t h0, l0, h1, l1;
        split_pair(v.x, v.y, h0, l0);
        split_pair(v.z, v.w, h1, l1);
        const int off = r * KPITCH + c4 * 4;
        *(uint32_t*)&Khs[off]     = h0;  *(uint32_t*)&Khs[off + 2] = h1;
        *(uint32_t*)&Kls[off]     = l0;  *(uint32_t*)&Kls[off + 2] = l1;
    }
    __syncthreads();
    uint32_t qh[2][4], ql[2][4];
#pragma unroll
    for (int kb = 0; kb < 2; kb++) {
        const int row = w * 16 + (lane & 15);
        const uint32_t byt =
            (uint32_t)(row * KPITCH + kb * 16 + ((lane >> 4) << 3)) * 2;
        ldsm4(qh[kb], aKh + byt);
        ldsm4(ql[kb], aKl + byt);
    }
    __syncthreads();

    float m[2] = {-INFINITY, -INFINITY}, l[2] = {0.f, 0.f};
    float o[4][4];
#pragma unroll
    for (int jd = 0; jd < 4; jd++)
#pragma unroll
        for (int u = 0; u < 4; u++) o[jd][u] = 0.f;

    const float* sphb = sph + (size_t)b*Ss*Ss + (size_t)q0*Ss;

    for (int k0 = 0; k0 < Ss; k0 += 64) {
        // ---- load K/V tile (split) + bias tile ----
#pragma unroll
        for (int j = 0; j < 4; j++) {
            const int idx = tid + j * 128;
            const int r = idx >> 3, c4 = idx & 7;
            const size_t gi = (size_t)((b*Ss + k0 + r) * Dd + h * 32 + c4 * 4);
            float4 kv = *(const float4*)(K + gi);
            float4 vv = *(const float4*)(V + gi);
            uint32_t h0, l0, h1, l1;
            const int off = r * KPITCH + c4 * 4;
            split_pair(kv.x, kv.y, h0, l0);
            split_pair(kv.z, kv.w, h1, l1);
            *(uint32_t*)&Khs[off]     = h0;  *(uint32_t*)&Khs[off + 2] = h1;
            *(uint32_t*)&Kls[off]     = l0;  *(uint32_t*)&Kls[off + 2] = l1;
            split_pair(vv.x, vv.y, h0, l0);
            split_pair(vv.z, vv.w, h1, l1);
            *(uint32_t*)&Vhs[off]     = h0;  *(uint32_t*)&Vhs[off + 2] = h1;
            *(uint32_t*)&Vls[off]     = l0;  *(uint32_t*)&Vls[off + 2] = l1;
        }
#pragma unroll
        for (int j = 0; j < 8; j++) {
            const int idx = tid + j * 128;          // 1024 float4
            const int r = idx >> 4, c4 = idx & 15;
            *(float4*)&Bs[r * SPITCH + c4 * 4] =
                *(const float4*)(sphb + (size_t)r * Ss + k0 + c4 * 4);
        }
        __syncthreads();

        // ---- S = Q K^T (bf16x3) ----
        float s[8][4];
#pragma unroll
        for (int j = 0; j < 8; j++)
#pragma unroll
            for (int u = 0; u < 4; u++) s[j][u] = 0.f;

        const int r8 = lane & 7, hi8 = ((lane & 15) >> 3);
#pragma unroll
        for (int j = 0; j < 8; j++) {
#pragma unroll
            for (int kb = 0; kb < 2; kb++) {
                uint32_t bh[2], bl[2];
                const uint32_t byt =
                    (uint32_t)((j*8 + r8) * KPITCH + kb * 16 + hi8 * 8) * 2;
                ldsm2(bh, aKh + byt);
                ldsm2(bl, aKl + byt);
                mma_bf(s[j], qh[kb], bh);
                mma_bf(s[j], qh[kb], bl);
                mma_bf(s[j], ql[kb], bh);
            }
        }

        // ---- bias + online softmax ----
        float rmax0 = -INFINITY, rmax1 = -INFINITY;
#pragma unroll
        for (int j = 0; j < 8; j++) {
            const int col = j * 8 + tig * 2;
            float2 b0 = *(float2*)&Bs[(w*16 + gid)     * SPITCH + col];
            float2 b1 = *(float2*)&Bs[(w*16 + gid + 8) * SPITCH + col];
            s[j][0] += b0.x; s[j][1] += b0.y;
            s[j][2] += b1.x; s[j][3] += b1.y;
            rmax0 = fmaxf(rmax0, fmaxf(s[j][0], s[j][1]));
            rmax1 = fmaxf(rmax1, fmaxf(s[j][2], s[j][3]));
        }
        rmax0 = fmaxf(rmax0, __shfl_xor_sync(0xffffffffu, rmax0, 1));
        rmax0 = fmaxf(rmax0, __shfl_xor_sync(0xffffffffu, rmax0, 2));
        rmax1 = fmaxf(rmax1, __shfl_xor_sync(0xffffffffu, rmax1, 1));
        rmax1 = fmaxf(rmax1, __shfl_xor_sync(0xffffffffu, rmax1, 2));

        const float mn0 = fmaxf(m[0], rmax0), mn1 = fmaxf(m[1], rmax1);
        const float al0 = __expf(m[0] - mn0), al1 = __expf(m[1] - mn1);
        m[0] = mn0; m[1] = mn1;

        float ps0 = 0.f, ps1 = 0.f;
        uint32_t ph[4][4], pl[4][4];
#pragma unroll
        for (int j = 0; j < 8; j++) {
            float p0 = __expf(s[j][0] - mn0), p1 = __expf(s[j][1] - mn0);
            float p2 = __expf(s[j][2] - mn1), p3 = __expf(s[j][3] - mn1);
            ps0 += p0 + p1; ps1 += p2 + p3;
            uint32_t hA, lA, hB, lB;
            split_pair(p0, p1, hA, lA);
            split_pair(p2, p3, hB, lB);
            const int kb = j >> 1;
            if (!(j & 1)) { ph[kb][0] = hA; pl[kb][0] = lA;
                            ph[kb][1] = hB; pl[kb][1] = lB; }
            else          { ph[kb][2] = hA; pl[kb][2] = lA;
                            ph[kb][3] = hB; pl[kb][3] = lB; }
        }
        ps0 += __shfl_xor_sync(0xffffffffu, ps0, 1);
        ps0 += __shfl_xor_sync(0xffffffffu, ps0, 2);
        ps1 += __shfl_xor_sync(0xffffffffu, ps1, 1);
        ps1 += __shfl_xor_sync(0xffffffffu, ps1, 2);
        l[0] = l[0] * al0 + ps0;
        l[1] = l[1] * al1 + ps1;
#pragma unroll
        for (int jd = 0; jd < 4; jd++) {
            o[jd][0] *= al0; o[jd][1] *= al0;
            o[jd][2] *= al1; o[jd][3] *= al1;
        }

        // ---- O += P V (bf16x3) ----
#pragma unroll
        for (int kb = 0; kb < 4; kb++) {
#pragma unroll
            for (int jd = 0; jd < 4; jd++) {
                uint32_t vh[2], vl[2];
                const uint32_t byt =
                    (uint32_t)((kb*16 + (lane & 15)) * KPITCH + jd * 8) * 2;
                ldsm2t(vh, aVh + byt);
                ldsm2t(vl, aVl + byt);
                mma_bf(o[jd], ph[kb], vh);
                mma_bf(o[jd], ph[kb], vl);
                mma_bf(o[jd], pl[kb], vh);
            }
        }
        __syncthreads();
    }

    const float inv0 = 1.f / l[0], inv1 = 1.f / l[1];
    const int r0 = b*Ss + q0 + w*16 + gid;
#pragma unroll
    for (int jd = 0; jd < 4; jd++) {
        const int col = h * 32 + jd * 8 + tig * 2;
        *(float2*)(O + (size_t)r0 * Dd + col) =
            make_float2(o[jd][0] * inv0, o[jd][1] * inv0);
        *(float2*)(O + (size_t)(r0 + 8) * Dd + col) =
            make_float2(o[jd][2] * inv1, o[jd][3] * inv1);
    }
}

// ---------------- fused residual + LayerNorm -------------------------------
__global__ __launch_bounds__(256) void add_ln(
    const float* __restrict__ x, const float* __restrict__ s,
    const float* __restrict__ g, const float* __restrict__ bb,
    float* __restrict__ out)
{
    const int row = blockIdx.x;
    const int t   = threadIdx.x;
    const size_t idx = (size_t)row * Dd + t;
    const float v = x[idx] + s[idx];

    float sum = v, sq = v * v;
#pragma unroll
    for (int o = 16; o; o >>= 1) {
        sum += __shfl_xor_sync(0xffffffffu, sum, o);
        sq  += __shfl_xor_sync(0xffffffffu, sq,  o);
    }
    __shared__ float ssum[8], ssq[8];
    const int w = t >> 5, lane = t & 31;
    if (lane == 0) { ssum[w] = sum; ssq[w] = sq; }
    __syncthreads();
    if (w == 0) {
        float a = (lane < 8) ? ssum[lane] : 0.f;
        float c = (lane < 8) ? ssq[lane]  : 0.f;
#pragma unroll
        for (int o = 4; o; o >>= 1) {
            a += __shfl_xor_sync(0xffffffffu, a, o);
            c += __shfl_xor_sync(0xffffffffu, c, o);
        }
        if (lane == 0) { ssum[0] = a; ssq[0] = c; }
    }
    __syncthreads();
    const float mu  = ssum[0] * (1.f / Dd);
    const float var = ssq[0]  * (1.f / Dd) - mu * mu;
    out[idx] = (v - mu) * rsqrtf(var + 1e-5f) * g[t] + bb[t];
}

// ---------------- driver ----------------------------------------------------
extern "C" void kernel_launch(void* const* d_in, const int* in_sizes, int n_in,
                              void* d_out, int out_size)
{
    const float* src = (const float*)d_in[0];
    const float* sph = (const float*)d_in[1];
    const float* Wq  = (const float*)d_in[2];
    const float* bq  = (const float*)d_in[3];
    const float* Wk  = (const float*)d_in[4];
    const float* bk  = (const float*)d_in[5];
    const float* Wv  = (const float*)d_in[6];
    const float* bv  = (const float*)d_in[7];
    const float* Wo  = (const float*)d_in[8];
    const float* bo  = (const float*)d_in[9];
    const float* W1  = (const float*)d_in[10];
    const float* b1  = (const float*)d_in[11];
    const float* W2  = (const float*)d_in[12];
    const float* b2  = (const float*)d_in[13];
    const float* g1  = (const float*)d_in[14];
    const float* be1 = (const float*)d_in[15];
    const float* g2  = (const float*)d_in[16];
    const float* be2 = (const float*)d_in[17];
    float* out = (float*)d_out;

    float *X, *Qb, *Kb, *Vb, *Cb, *Tb, *Hb;
    cudaGetSymbolAddress((void**)&X,  g_X);
    cudaGetSymbolAddress((void**)&Qb, g_Qb);
    cudaGetSymbolAddress((void**)&Kb, g_Kb);
    cudaGetSymbolAddress((void**)&Vb, g_Vb);
    cudaGetSymbolAddress((void**)&Cb, g_Cb);
    cudaGetSymbolAddress((void**)&Tb, g_Tb);
    cudaGetSymbolAddress((void**)&Hb, g_Hf);

    cudaMemcpyAsync(X, src, sizeof(float) * (size_t)Mm * Dd,
                    cudaMemcpyDeviceToDevice);

    const dim3 gD (Dd/128,   Mm/128);   // 2  x 128
    const dim3 gF1(DFFf/128, Mm/128);   // 8  x 128
    const dim3 gAt(Ss/64, Hh, Bb);      // 32 x 8 x 8

    for (int i = 0; i < Ll; i++) {
        const float* wq = Wq + (size_t)i*Dd*Dd;
        const float* wk = Wk + (size_t)i*Dd*Dd;
        const float* wv = Wv + (size_t)i*Dd*Dd;
        const float* wo = Wo + (size_t)i*Dd*Dd;
        const float* w1 = W1 + (size_t)i*Dd*DFFf;
        const float* w2 = W2 + (size_t)i*DFFf*Dd;

        gemm_mma<<<gD, 256>>>(X,  wq, bq + i*Dd, Qb, Dd, Dd, 0);
        gemm_mma<<<gD, 256>>>(X,  wk, bk + i*Dd, Kb, Dd, Dd, 0);
        gemm_mma<<<gD, 256>>>(X,  wv, bv + i*Dd, Vb, Dd, Dd, 0);

        attn_mma<<<gAt, 128>>>(Qb, Kb, Vb, sph, Cb);

        gemm_mma<<<gD, 256>>>(Cb, wo, bo + i*Dd, Tb, Dd, Dd, 0);
        add_ln<<<Mm, Dd>>>(X, Tb, g1 + i*Dd, be1 + i*Dd, X);

        gemm_mma<<<gF1, 256>>>(X,  w1, b1 + i*DFFf, Hb, DFFf, Dd, 1);
        gemm_mma<<<gD, 256>>>(Hb, w2, b2 + i*Dd,   Tb, Dd, DFFf, 0);
        add_ln<<<Mm, Dd>>>(X, Tb, g2 + i*Dd, be2 + i*Dd, (i == Ll-1) ? out : X);
    }
}